// round 7
// baseline (speedup 1.0000x reference)
#include <cuda_runtime.h>
#include <cstdint>

#define NN 100000
#define NE 1600000
#define FD 64
#define NB_SCAN 98     // ceil(NN/1024)
#define NTILES 782     // ceil(NN/128)

// ---------------- device scratch (allocation-free contract) ----------------
__device__ int   g_flag32;
__device__ int   g_edges[2 * NE];
__device__ int   g_cnt[NN];
__device__ int   g_rowptr[NN + 1];
__device__ int   g_part[128];
__device__ int   g_srcs[NE];
__device__ float g_P [(size_t)NN * FD];
__device__ float g_Q [(size_t)NN * FD];
__device__ float g_h1[(size_t)NN * FD];

// ---------------- helpers ----------------
__device__ __forceinline__ float cvt_tf32(float x) {
    uint32_t u;
    asm("cvt.rna.tf32.f32 %0, %1;" : "=r"(u) : "f"(x));
    return __uint_as_float(u);
}
__device__ __forceinline__ void mma_tf32(float* d, const uint32_t* a, const uint32_t* b) {
    asm volatile(
        "mma.sync.aligned.m16n8k8.row.col.f32.tf32.tf32.f32 "
        "{%0,%1,%2,%3}, {%4,%5,%6,%7}, {%8,%9}, {%0,%1,%2,%3};"
        : "+f"(d[0]), "+f"(d[1]), "+f"(d[2]), "+f"(d[3])
        : "r"(a[0]), "r"(a[1]), "r"(a[2]), "r"(a[3]), "r"(b[0]), "r"(b[1]));
}

// ---------------- edge dtype detection + normalization ----------------
__global__ void k_detect(const void* __restrict__ ei_raw) {
    if (threadIdx.x == 0) g_flag32 = 0;
    __syncthreads();
    const long long* e64 = (const long long*)ei_raw;
    long long v = e64[threadIdx.x & 4095];
    if (v < 0 || v >= NN) atomicOr(&g_flag32, 1);
}
__global__ void k_convert(const void* __restrict__ ei_raw) {
    int i = blockIdx.x * blockDim.x + threadIdx.x;
    if (i >= 2 * NE) return;
    if (g_flag32) g_edges[i] = ((const int*)ei_raw)[i];
    else          g_edges[i] = (int)((const long long*)ei_raw)[i];
}

// ---------------- CSR build ----------------
__global__ void k_zero() {
    int i = blockIdx.x * blockDim.x + threadIdx.x;
    if (i < NN) g_cnt[i] = 0;
}
__global__ void k_hist() {
    int e = blockIdx.x * blockDim.x + threadIdx.x;
    if (e < NE) atomicAdd(&g_cnt[g_edges[NE + e]], 1);
}
__global__ void k_scan1() {
    __shared__ int s_w[32];
    int tid = threadIdx.x, idx = blockIdx.x * 1024 + tid;
    int lane = tid & 31, wid = tid >> 5;
    int v = (idx < NN) ? g_cnt[idx] : 0;
    int inc = v;
#pragma unroll
    for (int o = 1; o < 32; o <<= 1) {
        int t = __shfl_up_sync(0xffffffffu, inc, o);
        if (lane >= o) inc += t;
    }
    if (lane == 31) s_w[wid] = inc;
    __syncthreads();
    if (wid == 0) {
        int w = s_w[lane];
#pragma unroll
        for (int o = 1; o < 32; o <<= 1) {
            int t = __shfl_up_sync(0xffffffffu, w, o);
            if (lane >= o) w += t;
        }
        s_w[lane] = w;
    }
    __syncthreads();
    int boff = wid ? s_w[wid - 1] : 0;
    if (idx < NN) g_rowptr[idx] = inc - v + boff;
    if (tid == 0) g_part[blockIdx.x] = s_w[31];
}
__global__ void k_scan2() {
    __shared__ int s[128];
    int tid = threadIdx.x;
    s[tid] = (tid < NB_SCAN) ? g_part[tid] : 0;
    __syncthreads();
    if (tid == 0) {
        int run = 0;
        for (int i = 0; i < NB_SCAN; i++) { int t = s[i]; s[i] = run; run += t; }
    }
    __syncthreads();
    if (tid < NB_SCAN) g_part[tid] = s[tid];
}
__global__ void k_scan3() {
    int i = blockIdx.x * blockDim.x + threadIdx.x;
    if (i < NN) {
        int v = g_rowptr[i] + g_part[i >> 10];
        g_rowptr[i] = v;
        g_cnt[i]    = v;
    } else if (i == NN) {
        g_rowptr[NN] = NE;
    }
}
__global__ void k_scatter() {
    int e = blockIdx.x * blockDim.x + threadIdx.x;
    if (e < NE) {
        int src = g_edges[e];
        int dst = g_edges[NE + e];
        int pos = atomicAdd(&g_cnt[dst], 1);
        g_srcs[pos] = src;
    }
}

// ---------------- HMMA tf32x3 GEMM: P = X@Wa, Q = X@Wr + b ----------------
// block: 128 rows. warps 0-3 -> P (rows w*32..), warps 4-7 -> Q.
// each warp: 32 rows x 64 cols, K=64, m16n8k8, tf32 hi/lo 3-pass.
#define XPAD 68
#define WPAD 72
#define OFF_XH 0
#define OFF_XL (128 * XPAD)                     // floats
#define OFF_W  (2 * 128 * XPAD)                 // 4 mats of 64*WPAD
#define OFF_B  (OFF_W + 4 * 64 * WPAD)
#define GEMM_SMEM ((OFF_B + 64) * 4)

__global__ __launch_bounds__(256, 1) void k_gemm_mma(
    const float* __restrict__ X, const float* __restrict__ Wa,
    const float* __restrict__ Wr, const float* __restrict__ bias,
    float* __restrict__ P, float* __restrict__ Q) {
    extern __shared__ float sm[];
    float* sXh = sm + OFF_XH;
    float* sXl = sm + OFF_XL;
    float* sW  = sm + OFF_W;     // [Wa_h, Wa_l, Wr_h, Wr_l] each [64][WPAD]
    float* sb  = sm + OFF_B;

    int tid = threadIdx.x, wid = tid >> 5, lane = tid & 31;
    int base = blockIdx.x * 128;

    // fill X hi/lo
    for (int i = tid; i < 128 * 64; i += 256) {
        int r = i >> 6, k = i & 63;
        int row = base + r;
        float v = (row < NN) ? X[(size_t)row * 64 + k] : 0.f;
        float hi = cvt_tf32(v);
        float lo = cvt_tf32(v - hi);
        sXh[r * XPAD + k] = hi;
        sXl[r * XPAD + k] = lo;
    }
    // fill W hi/lo: W[k][n] row-major
    for (int i = tid; i < 64 * 64; i += 256) {
        int k = i >> 6, n = i & 63;
        float wa = Wa[i], wr = Wr[i];
        float wah = cvt_tf32(wa), wal = cvt_tf32(wa - wah);
        float wrh = cvt_tf32(wr), wrl = cvt_tf32(wr - wrh);
        sW[0 * 64 * WPAD + k * WPAD + n] = wah;
        sW[1 * 64 * WPAD + k * WPAD + n] = wal;
        sW[2 * 64 * WPAD + k * WPAD + n] = wrh;
        sW[3 * 64 * WPAD + k * WPAD + n] = wrl;
    }
    if (tid < 64) sb[tid] = bias[tid];
    __syncthreads();

    int mat = wid >> 2;            // 0 -> P/Wa, 1 -> Q/Wr
    int r0  = (wid & 3) * 32;
    int g = lane >> 2, t = lane & 3;

    float acc[2][8][4];
#pragma unroll
    for (int i = 0; i < 2; i++)
#pragma unroll
        for (int j = 0; j < 8; j++)
#pragma unroll
            for (int c = 0; c < 4; c++) acc[i][j][c] = 0.f;

#pragma unroll
    for (int pass = 0; pass < 3; pass++) {
        const float* A = (pass == 2) ? sXl : sXh;
        const float* B = sW + (mat * 2 + (pass == 1 ? 1 : 0)) * 64 * WPAD;
#pragma unroll
        for (int kt = 0; kt < 8; kt++) {
            int k0 = kt * 8;
            uint32_t bf[8][2];
#pragma unroll
            for (int j = 0; j < 8; j++) {
                bf[j][0] = __float_as_uint(B[(k0 + t)     * WPAD + j * 8 + g]);
                bf[j][1] = __float_as_uint(B[(k0 + t + 4) * WPAD + j * 8 + g]);
            }
            uint32_t af[2][4];
#pragma unroll
            for (int i = 0; i < 2; i++) {
                int rr = r0 + i * 16 + g;
                af[i][0] = __float_as_uint(A[rr       * XPAD + k0 + t]);
                af[i][1] = __float_as_uint(A[(rr + 8) * XPAD + k0 + t]);
                af[i][2] = __float_as_uint(A[rr       * XPAD + k0 + t + 4]);
                af[i][3] = __float_as_uint(A[(rr + 8) * XPAD + k0 + t + 4]);
            }
#pragma unroll
            for (int i = 0; i < 2; i++)
#pragma unroll
                for (int j = 0; j < 8; j++)
                    mma_tf32(acc[i][j], af[i], bf[j]);
        }
    }

    // epilogue: d0,d1 -> (row, 2t),(row, 2t+1); d2,d3 -> row+8
    float* out = mat ? Q : P;
#pragma unroll
    for (int i = 0; i < 2; i++) {
        int rA = base + r0 + i * 16 + g;
        int rB = rA + 8;
#pragma unroll
        for (int j = 0; j < 8; j++) {
            int col = j * 8 + t * 2;
            float bx = mat ? sb[col] : 0.f;
            float by = mat ? sb[col + 1] : 0.f;
            if (rA < NN)
                *(float2*)(out + (size_t)rA * 64 + col) =
                    make_float2(acc[i][j][0] + bx, acc[i][j][1] + by);
            if (rB < NN)
                *(float2*)(out + (size_t)rB * 64 + col) =
                    make_float2(acc[i][j][2] + bx, acc[i][j][3] + by);
        }
    }
}

// ---------------- fused agg: h = relu(mean-gather(P) + Q) ----------------
__global__ void k_agg_relu(const float* __restrict__ P, const float* __restrict__ Q,
                           float* __restrict__ h) {
    int warp = (blockIdx.x * blockDim.x + threadIdx.x) >> 5;
    int lane = threadIdx.x & 31;
    if (warp >= NN) return;
    int beg = g_rowptr[warp], end = g_rowptr[warp + 1];
    float2 a = make_float2(0.f, 0.f);
    for (int e = beg; e < end; e++) {
        int s = g_srcs[e];
        float2 v = *(const float2*)(P + (size_t)s * FD + 2 * lane);
        a.x += v.x; a.y += v.y;
    }
    float inv = (end > beg) ? 1.f / (float)(end - beg) : 0.f;
    float2 q = *(const float2*)(Q + (size_t)warp * FD + 2 * lane);
    float2 o;
    o.x = fmaxf(a.x * inv + q.x, 0.f);
    o.y = fmaxf(a.y * inv + q.y, 0.f);
    *(float2*)(h + (size_t)warp * FD + 2 * lane) = o;
}

// ---------------- fused agg + head: out = relu(mean(P)+Q) @ Wl + bl ----------------
__global__ void k_agg_final(const float* __restrict__ P, const float* __restrict__ Q,
                            const float* __restrict__ Wl, const float* __restrict__ bl,
                            float* __restrict__ out) {
    int warp = (blockIdx.x * blockDim.x + threadIdx.x) >> 5;
    int lane = threadIdx.x & 31;
    if (warp >= NN) return;
    int beg = g_rowptr[warp], end = g_rowptr[warp + 1];
    float2 a = make_float2(0.f, 0.f);
    for (int e = beg; e < end; e++) {
        int s = g_srcs[e];
        float2 v = *(const float2*)(P + (size_t)s * FD + 2 * lane);
        a.x += v.x; a.y += v.y;
    }
    float inv = (end > beg) ? 1.f / (float)(end - beg) : 0.f;
    float2 q = *(const float2*)(Q + (size_t)warp * FD + 2 * lane);
    float h0 = fmaxf(a.x * inv + q.x, 0.f);
    float h1 = fmaxf(a.y * inv + q.y, 0.f);
    float4 w = *(const float4*)(Wl + 4 * lane);
    float a0 = h0 * w.x + h1 * w.z;
    float a1 = h0 * w.y + h1 * w.w;
#pragma unroll
    for (int o = 16; o; o >>= 1) {
        a0 += __shfl_xor_sync(0xffffffffu, a0, o);
        a1 += __shfl_xor_sync(0xffffffffu, a1, o);
    }
    if (lane == 0) {
        out[(size_t)warp * 2 + 0] = a0 + bl[0];
        out[(size_t)warp * 2 + 1] = a1 + bl[1];
    }
}

// ---------------- launch ----------------
extern "C" void kernel_launch(void* const* d_in, const int* in_sizes, int n_in,
                              void* d_out, int out_size) {
    const float* x   = (const float*)d_in[0];
    const void*  ei  = d_in[1];
    const float* W1a = (const float*)d_in[2];
    const float* W1r = (const float*)d_in[3];
    const float* b1  = (const float*)d_in[4];
    const float* W2a = (const float*)d_in[5];
    const float* W2r = (const float*)d_in[6];
    const float* b2  = (const float*)d_in[7];
    const float* Wl  = (const float*)d_in[8];
    const float* bl  = (const float*)d_in[9];
    float*       out = (float*)d_out;

    (void)in_sizes; (void)n_in; (void)out_size;

    cudaFuncSetAttribute(k_gemm_mma, cudaFuncAttributeMaxDynamicSharedMemorySize, GEMM_SMEM);

    float *P, *Q, *h1;
    cudaGetSymbolAddress((void**)&P,  g_P);
    cudaGetSymbolAddress((void**)&Q,  g_Q);
    cudaGetSymbolAddress((void**)&h1, g_h1);

    // ---- edge dtype normalize + CSR build ----
    k_detect <<<1, 1024>>>(ei);
    k_convert<<<(2 * NE + 255) / 256, 256>>>(ei);
    k_zero   <<<(NN + 255) / 256, 256>>>();
    k_hist   <<<NE / 256, 256>>>();
    k_scan1  <<<NB_SCAN, 1024>>>();
    k_scan2  <<<1, 128>>>();
    k_scan3  <<<(NN + 1 + 255) / 256, 256>>>();
    k_scatter<<<NE / 256, 256>>>();

    // ---- layer 1 ----
    k_gemm_mma<<<NTILES, 256, GEMM_SMEM>>>(x, W1a, W1r, b1, P, Q);
    k_agg_relu<<<12500, 256>>>(P, Q, h1);

    // ---- layer 2 + fused head ----
    k_gemm_mma <<<NTILES, 256, GEMM_SMEM>>>(h1, W2a, W2r, b2, P, Q);
    k_agg_final<<<12500, 256>>>(P, Q, Wl, bl, out);
}

// round 9
// speedup vs baseline: 1.3253x; 1.3253x over previous
#include <cuda_runtime.h>
#include <cstdint>

#define NN 100000
#define NE 1600000
#define FD 64
#define NB_SCAN 98     // ceil(NN/1024)
#define NTILES 782     // ceil(NN/128)

// ---------------- device scratch (allocation-free contract) ----------------
__device__ int   g_flag32;
__device__ int   g_edges[2 * NE];
__device__ int   g_cnt[NN];
__device__ int   g_rowptr[NN + 1];
__device__ int   g_part[128];
__device__ int   g_srcs[NE];
__device__ float g_P [(size_t)NN * FD];
__device__ float g_Q [(size_t)NN * FD];
__device__ float g_h1[(size_t)NN * FD];

// ---------------- helpers ----------------
__device__ __forceinline__ float cvt_tf32(float x) {
    uint32_t u;
    asm("cvt.rna.tf32.f32 %0, %1;" : "=r"(u) : "f"(x));
    return __uint_as_float(u);
}
__device__ __forceinline__ void mma_tf32(float* d, const uint32_t* a, const uint32_t* b) {
    asm volatile(
        "mma.sync.aligned.m16n8k8.row.col.f32.tf32.tf32.f32 "
        "{%0,%1,%2,%3}, {%4,%5,%6,%7}, {%8,%9}, {%0,%1,%2,%3};"
        : "+f"(d[0]), "+f"(d[1]), "+f"(d[2]), "+f"(d[3])
        : "r"(a[0]), "r"(a[1]), "r"(a[2]), "r"(a[3]), "r"(b[0]), "r"(b[1]));
}

// ---------------- edge dtype detection ----------------
__global__ void k_detect(const void* __restrict__ ei_raw) {
    if (threadIdx.x == 0) g_flag32 = 0;
    __syncthreads();
    const long long* e64 = (const long long*)ei_raw;
    long long v = e64[threadIdx.x & 4095];
    if (v < 0 || v >= NN) atomicOr(&g_flag32, 1);
}

// ---------------- CSR build ----------------
__global__ void k_zero() {
    int i = blockIdx.x * blockDim.x + threadIdx.x;
    if (i < NN) g_cnt[i] = 0;
}
__global__ void k_convert_hist(const void* __restrict__ ei_raw) {  // normalize + dst histogram
    int i = blockIdx.x * blockDim.x + threadIdx.x;
    if (i >= 2 * NE) return;
    int v = g_flag32 ? ((const int*)ei_raw)[i]
                     : (int)((const long long*)ei_raw)[i];
    g_edges[i] = v;
    if (i >= NE) atomicAdd(&g_cnt[v], 1);
}
__global__ void k_scan1() {
    __shared__ int s_w[32];
    int tid = threadIdx.x, idx = blockIdx.x * 1024 + tid;
    int lane = tid & 31, wid = tid >> 5;
    int v = (idx < NN) ? g_cnt[idx] : 0;
    int inc = v;
#pragma unroll
    for (int o = 1; o < 32; o <<= 1) {
        int t = __shfl_up_sync(0xffffffffu, inc, o);
        if (lane >= o) inc += t;
    }
    if (lane == 31) s_w[wid] = inc;
    __syncthreads();
    if (wid == 0) {
        int w = s_w[lane];
#pragma unroll
        for (int o = 1; o < 32; o <<= 1) {
            int t = __shfl_up_sync(0xffffffffu, w, o);
            if (lane >= o) w += t;
        }
        s_w[lane] = w;
    }
    __syncthreads();
    int boff = wid ? s_w[wid - 1] : 0;
    if (idx < NN) g_rowptr[idx] = inc - v + boff;
    if (tid == 0) g_part[blockIdx.x] = s_w[31];
}
__global__ void k_scan2() {
    __shared__ int s[128];
    int tid = threadIdx.x;
    s[tid] = (tid < NB_SCAN) ? g_part[tid] : 0;
    __syncthreads();
    if (tid == 0) {
        int run = 0;
        for (int i = 0; i < NB_SCAN; i++) { int t = s[i]; s[i] = run; run += t; }
    }
    __syncthreads();
    if (tid < NB_SCAN) g_part[tid] = s[tid];
}
__global__ void k_scan3() {
    int i = blockIdx.x * blockDim.x + threadIdx.x;
    if (i < NN) {
        int v = g_rowptr[i] + g_part[i >> 10];
        g_rowptr[i] = v;
        g_cnt[i]    = v;
    } else if (i == NN) {
        g_rowptr[NN] = NE;
    }
}
__global__ void k_scatter() {
    int e = blockIdx.x * blockDim.x + threadIdx.x;
    if (e < NE) {
        int src = g_edges[e];
        int dst = g_edges[NE + e];
        int pos = atomicAdd(&g_cnt[dst], 1);
        g_srcs[pos] = src;
    }
}

// ---------------- HMMA tf32x3 GEMM: P = X@Wa, Q = X@Wr + b ----------------
// 256 threads, 128-row tile. warps 0-3 -> P, warps 4-7 -> Q (32 rows x 64 cols each).
// X kept fp32 in smem (hi/lo split in registers). W pre-scattered to fragment-major
// layout -> conflict-free LDS.64 B-fragment loads, no padding.
// smem = 34.8KB (X) + 64KB (W frags) + bias ~= 100.6KB -> 2 CTAs/SM.
#define XPAD 68
#define OFF_WF (128 * XPAD)                  // floats; 4 frag mats of 4096 floats
#define OFF_B  (OFF_WF + 4 * 4096)
#define GEMM_SMEM ((OFF_B + 64) * 4)

__global__ __launch_bounds__(256, 2) void k_gemm_mma(
    const float* __restrict__ X, const float* __restrict__ Wa,
    const float* __restrict__ Wr, const float* __restrict__ bias,
    float* __restrict__ P, float* __restrict__ Q) {
    extern __shared__ float sm[];
    float* sX  = sm;                  // [128][XPAD] fp32
    float* sWf = sm + OFF_WF;         // [Wa_h, Wa_l, Wr_h, Wr_l] frag-major, 4096 each
    float* sb  = sm + OFF_B;

    int tid = threadIdx.x, wid = tid >> 5, lane = tid & 31;
    int base = blockIdx.x * 128;

    // X tile: pure float4 copy (row stride 272B, 16B aligned)
    for (int i = tid; i < 128 * 16; i += 256) {
        int r = i >> 4, c4 = i & 15;
        int row = base + r;
        float4 v = make_float4(0.f, 0.f, 0.f, 0.f);
        if (row < NN) v = *(const float4*)(X + (size_t)row * 64 + c4 * 4);
        *(float4*)(sX + r * XPAD + c4 * 4) = v;
    }
    // W: convert to tf32 hi/lo, scatter into fragment-major layout.
    // element (k,n): kt=k>>3, t=k&3, s=(k>>2)&1, j=n>>3, g=n&7, lane=g*4+t
    for (int i = tid; i < 2 * 64 * 64; i += 256) {
        int m = i >> 12, idx = i & 4095;
        int k = idx >> 6, n = idx & 63;
        float w = m ? Wr[idx] : Wa[idx];
        float hi = cvt_tf32(w);
        float lo = cvt_tf32(w - hi);
        int kt = k >> 3, t = k & 3, s = (k >> 2) & 1;
        int j = n >> 3, g = n & 7;
        int fi = ((kt * 8 + j) * 32 + (g * 4 + t)) * 2 + s;
        sWf[(2 * m + 0) * 4096 + fi] = hi;
        sWf[(2 * m + 1) * 4096 + fi] = lo;
    }
    if (tid < 64) sb[tid] = bias[tid];
    __syncthreads();

    int mat = wid >> 2;            // 0 -> P/Wa, 1 -> Q/Wr
    int r0  = (wid & 3) * 32;
    int g = lane >> 2, t = lane & 3;
    const float* Wh = sWf + (2 * mat + 0) * 4096;
    const float* Wl = sWf + (2 * mat + 1) * 4096;

    float acc[2][8][4];
#pragma unroll
    for (int i = 0; i < 2; i++)
#pragma unroll
        for (int j = 0; j < 8; j++)
#pragma unroll
            for (int c = 0; c < 4; c++) acc[i][j][c] = 0.f;

#pragma unroll
    for (int kt = 0; kt < 8; kt++) {
        int k0 = kt * 8;
        // A fragments: load fp32, split hi/lo in regs (bank-conflict-free: 4g+t)
        uint32_t ah[2][4], al[2][4];
#pragma unroll
        for (int i = 0; i < 2; i++) {
            int rr = r0 + i * 16 + g;
            float v[4];
            v[0] = sX[rr       * XPAD + k0 + t];
            v[1] = sX[(rr + 8) * XPAD + k0 + t];
            v[2] = sX[rr       * XPAD + k0 + t + 4];
            v[3] = sX[(rr + 8) * XPAD + k0 + t + 4];
#pragma unroll
            for (int c = 0; c < 4; c++) {
                float hi = cvt_tf32(v[c]);
                ah[i][c] = __float_as_uint(hi);
                al[i][c] = __float_as_uint(cvt_tf32(v[c] - hi));
            }
        }
        // B hi fragments: LDS.64, conflict-free
        uint32_t bf[8][2];
#pragma unroll
        for (int j = 0; j < 8; j++) {
            float2 f = *(const float2*)(Wh + ((kt * 8 + j) * 32 + lane) * 2);
            bf[j][0] = __float_as_uint(f.x);
            bf[j][1] = __float_as_uint(f.y);
        }
#pragma unroll
        for (int i = 0; i < 2; i++)
#pragma unroll
            for (int j = 0; j < 8; j++) mma_tf32(acc[i][j], ah[i], bf[j]);
#pragma unroll
        for (int i = 0; i < 2; i++)
#pragma unroll
            for (int j = 0; j < 8; j++) mma_tf32(acc[i][j], al[i], bf[j]);
        // B lo fragments (reuse regs)
#pragma unroll
        for (int j = 0; j < 8; j++) {
            float2 f = *(const float2*)(Wl + ((kt * 8 + j) * 32 + lane) * 2);
            bf[j][0] = __float_as_uint(f.x);
            bf[j][1] = __float_as_uint(f.y);
        }
#pragma unroll
        for (int i = 0; i < 2; i++)
#pragma unroll
            for (int j = 0; j < 8; j++) mma_tf32(acc[i][j], ah[i], bf[j]);
    }

    // epilogue: d0,d1 -> (row, 2t),(row, 2t+1); d2,d3 -> row+8
    float* out = mat ? Q : P;
#pragma unroll
    for (int i = 0; i < 2; i++) {
        int rA = base + r0 + i * 16 + g;
        int rB = rA + 8;
#pragma unroll
        for (int j = 0; j < 8; j++) {
            int col = j * 8 + t * 2;
            float bx = mat ? sb[col] : 0.f;
            float by = mat ? sb[col + 1] : 0.f;
            if (rA < NN)
                *(float2*)(out + (size_t)rA * 64 + col) =
                    make_float2(acc[i][j][0] + bx, acc[i][j][1] + by);
            if (rB < NN)
                *(float2*)(out + (size_t)rB * 64 + col) =
                    make_float2(acc[i][j][2] + bx, acc[i][j][3] + by);
        }
    }
}

// ---------------- fused agg: h = relu(mean-gather(P) + Q) ----------------
__global__ void k_agg_relu(const float* __restrict__ P, const float* __restrict__ Q,
                           float* __restrict__ h) {
    int warp = (blockIdx.x * blockDim.x + threadIdx.x) >> 5;
    int lane = threadIdx.x & 31;
    if (warp >= NN) return;
    int beg = g_rowptr[warp], end = g_rowptr[warp + 1];
    float2 a = make_float2(0.f, 0.f);
    for (int e = beg; e < end; e++) {
        int s = g_srcs[e];
        float2 v = *(const float2*)(P + (size_t)s * FD + 2 * lane);
        a.x += v.x; a.y += v.y;
    }
    float inv = (end > beg) ? 1.f / (float)(end - beg) : 0.f;
    float2 q = *(const float2*)(Q + (size_t)warp * FD + 2 * lane);
    float2 o;
    o.x = fmaxf(a.x * inv + q.x, 0.f);
    o.y = fmaxf(a.y * inv + q.y, 0.f);
    *(float2*)(h + (size_t)warp * FD + 2 * lane) = o;
}

// ---------------- fused agg + head: out = relu(mean(P)+Q) @ Wl + bl ----------------
__global__ void k_agg_final(const float* __restrict__ P, const float* __restrict__ Q,
                            const float* __restrict__ Wl, const float* __restrict__ bl,
                            float* __restrict__ out) {
    int warp = (blockIdx.x * blockDim.x + threadIdx.x) >> 5;
    int lane = threadIdx.x & 31;
    if (warp >= NN) return;
    int beg = g_rowptr[warp], end = g_rowptr[warp + 1];
    float2 a = make_float2(0.f, 0.f);
    for (int e = beg; e < end; e++) {
        int s = g_srcs[e];
        float2 v = *(const float2*)(P + (size_t)s * FD + 2 * lane);
        a.x += v.x; a.y += v.y;
    }
    float inv = (end > beg) ? 1.f / (float)(end - beg) : 0.f;
    float2 q = *(const float2*)(Q + (size_t)warp * FD + 2 * lane);
    float h0 = fmaxf(a.x * inv + q.x, 0.f);
    float h1 = fmaxf(a.y * inv + q.y, 0.f);
    float4 w = *(const float4*)(Wl + 4 * lane);
    float a0 = h0 * w.x + h1 * w.z;
    float a1 = h0 * w.y + h1 * w.w;
#pragma unroll
    for (int o = 16; o; o >>= 1) {
        a0 += __shfl_xor_sync(0xffffffffu, a0, o);
        a1 += __shfl_xor_sync(0xffffffffu, a1, o);
    }
    if (lane == 0) {
        out[(size_t)warp * 2 + 0] = a0 + bl[0];
        out[(size_t)warp * 2 + 1] = a1 + bl[1];
    }
}

// ---------------- launch ----------------
extern "C" void kernel_launch(void* const* d_in, const int* in_sizes, int n_in,
                              void* d_out, int out_size) {
    const float* x   = (const float*)d_in[0];
    const void*  ei  = d_in[1];
    const float* W1a = (const float*)d_in[2];
    const float* W1r = (const float*)d_in[3];
    const float* b1  = (const float*)d_in[4];
    const float* W2a = (const float*)d_in[5];
    const float* W2r = (const float*)d_in[6];
    const float* b2  = (const float*)d_in[7];
    const float* Wl  = (const float*)d_in[8];
    const float* bl  = (const float*)d_in[9];
    float*       out = (float*)d_out;

    (void)in_sizes; (void)n_in; (void)out_size;

    cudaFuncSetAttribute(k_gemm_mma, cudaFuncAttributeMaxDynamicSharedMemorySize, GEMM_SMEM);

    float *P, *Q, *h1;
    cudaGetSymbolAddress((void**)&P,  g_P);
    cudaGetSymbolAddress((void**)&Q,  g_Q);
    cudaGetSymbolAddress((void**)&h1, g_h1);

    // ---- edge dtype normalize + CSR build ----
    k_detect      <<<1, 1024>>>(ei);
    k_zero        <<<(NN + 255) / 256, 256>>>();
    k_convert_hist<<<(2 * NE + 255) / 256, 256>>>(ei);
    k_scan1       <<<NB_SCAN, 1024>>>();
    k_scan2       <<<1, 128>>>();
    k_scan3       <<<(NN + 1 + 255) / 256, 256>>>();
    k_scatter     <<<NE / 256, 256>>>();

    // ---- layer 1 ----
    k_gemm_mma<<<NTILES, 256, GEMM_SMEM>>>(x, W1a, W1r, b1, P, Q);
    k_agg_relu<<<12500, 256>>>(P, Q, h1);

    // ---- layer 2 + fused head ----
    k_gemm_mma <<<NTILES, 256, GEMM_SMEM>>>(h1, W2a, W2r, b2, P, Q);
    k_agg_final<<<12500, 256>>>(P, Q, Wl, bl, out);
}